// round 3
// baseline (speedup 1.0000x reference)
#include <cuda_runtime.h>
#include <math.h>

#define N_NODES  100000
#define N_EDGES  3200000
#define N_GRAPHS 64
#define F_IN     128
#define HID      256
#define N_CLS    2

// ---------------------------------------------------------------------------
// Scratch
// ---------------------------------------------------------------------------
__device__ __align__(16) float g_dinv[N_NODES];
__device__ __align__(16) int   g_deg[N_NODES];
__device__ __align__(16) int   g_rowptr[N_NODES + 1];
__device__ __align__(16) int   g_cursor[N_NODES];
__device__ __align__(16) int2  g_csr[N_EDGES];          // {src, norm bits}
__device__ __align__(16) float g_buf1[(size_t)N_NODES * HID];
__device__ __align__(16) float g_buf2[(size_t)N_NODES * HID];
__device__ __align__(16) float g_sums[N_GRAPHS * HID];
__device__ float g_cnt[N_GRAPHS];
__device__ int   g_is64;

// ---------------------------------------------------------------------------
__device__ __forceinline__ void red_add_v4(float* p, float4 v) {
    asm volatile("red.global.add.v4.f32 [%0], {%1, %2, %3, %4};"
                 :: "l"(p), "f"(v.x), "f"(v.y), "f"(v.z), "f"(v.w) : "memory");
}
__device__ __forceinline__ int idx_at(const void* p, long long i, int is64) {
    return is64 ? (int)((const long long*)p)[i] : ((const int*)p)[i];
}
__device__ __forceinline__ void fma4(float4& a, float4 v, float w) {
    a.x += v.x * w; a.y += v.y * w; a.z += v.z * w; a.w += v.w * w;
}

// ---------------------------------------------------------------------------
// 1) prep: zero deg/sums/cnt, detect index dtype
// ---------------------------------------------------------------------------
__global__ void k_prep(const void* __restrict__ edges) {
    int i = blockIdx.x * blockDim.x + threadIdx.x;
    if (i < N_NODES) g_deg[i] = 0;
    if (i < N_GRAPHS * HID) g_sums[i] = 0.0f;
    if (i < N_GRAPHS) g_cnt[i] = 0.0f;
    if (i == 0) {
        const long long* p = (const long long*)edges;
        int is64 = 1;
        for (int j = 0; j < 512; j++) {
            long long v = p[j];
            if (v < 0 || v >= N_NODES) { is64 = 0; break; }
        }
        g_is64 = is64;
    }
}

// 2) degree count + per-graph node count
__global__ void k_deg_cnt(const void* __restrict__ edges, const void* __restrict__ batch) {
    int i = blockIdx.x * blockDim.x + threadIdx.x;
    int is64 = g_is64;
    if (i < N_EDGES) {
        int d = idx_at(edges, (long long)N_EDGES + i, is64);
        atomicAdd(&g_deg[d], 1);
    }
    if (i < N_NODES) {
        int g = idx_at(batch, i, is64);
        atomicAdd(&g_cnt[g], 1.0f);
    }
}

// 3) single-block scan -> rowptr/cursor, dinv = rsqrt(deg+1)
__global__ void k_scan_rsqrt() {
    const int T = 1024;
    const int CH = (N_NODES + T - 1) / T;
    __shared__ int part[T];
    int t = threadIdx.x;
    int base = t * CH;
    int local = 0;
    for (int i = 0; i < CH; i++) {
        int idx = base + i;
        if (idx < N_NODES) local += g_deg[idx];
    }
    part[t] = local;
    __syncthreads();
    for (int off = 1; off < T; off <<= 1) {
        int v = (t >= off) ? part[t - off] : 0;
        __syncthreads();
        if (t >= off) part[t] += v;
        __syncthreads();
    }
    int prefix = (t == 0) ? 0 : part[t - 1];
    for (int i = 0; i < CH; i++) {
        int idx = base + i;
        if (idx < N_NODES) {
            g_rowptr[idx] = prefix;
            g_cursor[idx] = prefix;
            prefix += g_deg[idx];
        }
    }
    if (t == T - 1) g_rowptr[N_NODES] = part[T - 1];
    __syncthreads();
    for (int i = t; i < N_NODES; i += T)
        g_dinv[i] = rsqrtf((float)(g_deg[i] + 1));
}

// 4) CSR fill: packed {src, norm}
__global__ void k_fill(const void* __restrict__ edges) {
    int e = blockIdx.x * blockDim.x + threadIdx.x;
    if (e >= N_EDGES) return;
    int is64 = g_is64;
    int s = idx_at(edges, e, is64);
    int d = idx_at(edges, (long long)N_EDGES + e, is64);
    int slot = atomicAdd(&g_cursor[d], 1);
    float nrm = g_dinv[s] * g_dinv[d];
    g_csr[slot] = make_int2(s, __float_as_int(nrm));
}

// ---------------------------------------------------------------------------
// Pull aggregation: one WARP per node, float4 per lane.
// out[d] = dinv[d]^2 * H[d] + sum_e nrm[e] * H[src[e]]
// ---------------------------------------------------------------------------
template <int F>
__global__ void __launch_bounds__(256) k_agg(const float* __restrict__ H,
                                             float* __restrict__ out) {
    constexpr int C = F / 128;   // float4 per lane
    int gw = (blockIdx.x * 256 + threadIdx.x) >> 5;
    int lane = threadIdx.x & 31;
    if (gw >= N_NODES) return;
    int beg = __ldg(&g_rowptr[gw]);
    int end = __ldg(&g_rowptr[gw + 1]);
    float di = __ldg(&g_dinv[gw]);
    float self = di * di;

    const float4* Hv = (const float4*)H;
    size_t rowq = (size_t)gw * (F / 4);

    float4 acc[C];
#pragma unroll
    for (int c = 0; c < C; c++) {
        float4 v = __ldg(&Hv[rowq + c * 32 + lane]);
        acc[c] = make_float4(v.x * self, v.y * self, v.z * self, v.w * self);
    }

    int j = beg;
    for (; j + 4 <= end; j += 4) {
        int2 e0 = __ldg(&g_csr[j + 0]);
        int2 e1 = __ldg(&g_csr[j + 1]);
        int2 e2 = __ldg(&g_csr[j + 2]);
        int2 e3 = __ldg(&g_csr[j + 3]);
        float n0 = __int_as_float(e0.y), n1 = __int_as_float(e1.y);
        float n2 = __int_as_float(e2.y), n3 = __int_as_float(e3.y);
#pragma unroll
        for (int c = 0; c < C; c++) {
            float4 v0 = __ldg(&Hv[(size_t)e0.x * (F / 4) + c * 32 + lane]);
            float4 v1 = __ldg(&Hv[(size_t)e1.x * (F / 4) + c * 32 + lane]);
            float4 v2 = __ldg(&Hv[(size_t)e2.x * (F / 4) + c * 32 + lane]);
            float4 v3 = __ldg(&Hv[(size_t)e3.x * (F / 4) + c * 32 + lane]);
            fma4(acc[c], v0, n0);
            fma4(acc[c], v1, n1);
            fma4(acc[c], v2, n2);
            fma4(acc[c], v3, n3);
        }
    }
    for (; j < end; j++) {
        int2 e = __ldg(&g_csr[j]);
        float n = __int_as_float(e.y);
#pragma unroll
        for (int c = 0; c < C; c++) {
            float4 v = __ldg(&Hv[(size_t)e.x * (F / 4) + c * 32 + lane]);
            fma4(acc[c], v, n);
        }
    }
#pragma unroll
    for (int c = 0; c < C; c++)
        ((float4*)out)[rowq + c * 32 + lane] = acc[c];
}

// ---------------------------------------------------------------------------
// SGEMM + bias + ReLU (+ optional fused mean-pool reduction).
// BM=128 BN=64 BK=16, 128 threads, 8x8/thread, double-buffered smem.
// ---------------------------------------------------------------------------
template <bool FUSE_POOL>
__global__ void __launch_bounds__(128) k_gemm(
    const float* __restrict__ A, const float* __restrict__ W,
    const float* __restrict__ bias, float* __restrict__ C_,
    const void* __restrict__ batch, int M, int N, int K) {
    constexpr int BM = 128, BN = 64, BK = 16, TM = 8, TN = 8;
    constexpr int TX = BN / TN;   // 8
    __shared__ float Ast[2][BK][BM];
    __shared__ float Ws[2][BK][BN];

    const int tid = threadIdx.x;
    const int tx = tid % TX;
    const int ty = tid / TX;      // 0..15
    const int row0 = blockIdx.y * BM;
    const int col0 = blockIdx.x * BN;

    float acc[TM][TN];
#pragma unroll
    for (int i = 0; i < TM; i++)
#pragma unroll
        for (int j = 0; j < TN; j++) acc[i][j] = 0.0f;

    // A-tile: 512 float4 -> 4 per thread. j = tid + it*128; m=j/4; k4=j%4.
    // W-tile: 256 float4 -> 2 per thread. j = tid + it*128; k=j/16; n4=j%16.
    float4 pa[4]; float4 pw[2];
    const int am = tid / 4;           // base m for A loads (per it: +32)
    const int ak4 = tid % 4;
    const int wk = tid / 16;          // base k for W loads (per it: +8)
    const int wn4 = tid % 16;

    auto load_tiles = [&](int k0) {
#pragma unroll
        for (int it = 0; it < 4; it++) {
            int gm = row0 + am + it * 32;
            pa[it] = make_float4(0.f, 0.f, 0.f, 0.f);
            if (gm < M) pa[it] = *(const float4*)(A + (size_t)gm * K + k0 + ak4 * 4);
        }
#pragma unroll
        for (int it = 0; it < 2; it++) {
            int k = wk + it * 8;
            pw[it] = *(const float4*)(W + (size_t)(k0 + k) * N + col0 + wn4 * 4);
        }
    };
    auto store_tiles = [&](int buf) {
#pragma unroll
        for (int it = 0; it < 4; it++) {
            int m = am + it * 32;
            Ast[buf][ak4 * 4 + 0][m] = pa[it].x;
            Ast[buf][ak4 * 4 + 1][m] = pa[it].y;
            Ast[buf][ak4 * 4 + 2][m] = pa[it].z;
            Ast[buf][ak4 * 4 + 3][m] = pa[it].w;
        }
#pragma unroll
        for (int it = 0; it < 2; it++)
            *(float4*)(&Ws[buf][wk + it * 8][wn4 * 4]) = pw[it];
    };

    const int NTILE = K / BK;
    load_tiles(0);
    store_tiles(0);
    __syncthreads();

    for (int t = 0; t < NTILE; t++) {
        int cur = t & 1;
        if (t + 1 < NTILE) load_tiles((t + 1) * BK);
#pragma unroll
        for (int k = 0; k < BK; k++) {
            float4 a0 = *(const float4*)(&Ast[cur][k][ty * TM]);
            float4 a1 = *(const float4*)(&Ast[cur][k][ty * TM + 4]);
            float4 w0 = *(const float4*)(&Ws[cur][k][tx * TN]);
            float4 w1 = *(const float4*)(&Ws[cur][k][tx * TN + 4]);
            float av[TM], wv[TN];
            av[0] = a0.x; av[1] = a0.y; av[2] = a0.z; av[3] = a0.w;
            av[4] = a1.x; av[5] = a1.y; av[6] = a1.z; av[7] = a1.w;
            wv[0] = w0.x; wv[1] = w0.y; wv[2] = w0.z; wv[3] = w0.w;
            wv[4] = w1.x; wv[5] = w1.y; wv[6] = w1.z; wv[7] = w1.w;
#pragma unroll
            for (int i = 0; i < TM; i++)
#pragma unroll
                for (int j = 0; j < TN; j++) acc[i][j] += av[i] * wv[j];
        }
        if (t + 1 < NTILE) store_tiles(1 - cur);
        __syncthreads();
    }

    // bias
    float bv[TN];
    {
        float4 b0 = *(const float4*)(bias + col0 + tx * TN);
        float4 b1 = *(const float4*)(bias + col0 + tx * TN + 4);
        bv[0] = b0.x; bv[1] = b0.y; bv[2] = b0.z; bv[3] = b0.w;
        bv[4] = b1.x; bv[5] = b1.y; bv[6] = b1.z; bv[7] = b1.w;
    }

    if (!FUSE_POOL) {
#pragma unroll
        for (int i = 0; i < TM; i++) {
            int gm = row0 + ty * TM + i;
            if (gm >= M) continue;
            float4 v0, v1;
            v0.x = fmaxf(acc[i][0] + bv[0], 0.f);
            v0.y = fmaxf(acc[i][1] + bv[1], 0.f);
            v0.z = fmaxf(acc[i][2] + bv[2], 0.f);
            v0.w = fmaxf(acc[i][3] + bv[3], 0.f);
            v1.x = fmaxf(acc[i][4] + bv[4], 0.f);
            v1.y = fmaxf(acc[i][5] + bv[5], 0.f);
            v1.z = fmaxf(acc[i][6] + bv[6], 0.f);
            v1.w = fmaxf(acc[i][7] + bv[7], 0.f);
            float* dst = C_ + (size_t)gm * N + col0 + tx * TN;
            *(float4*)(dst) = v0;
            *(float4*)(dst + 4) = v1;
        }
    } else {
        // fused mean-pool numerator: segment rows by graph id, red.v4 per segment
        int is64 = g_is64;
        int i = 0;
        while (i < TM) {
            int gm = row0 + ty * TM + i;
            if (gm >= M) break;
            int g = idx_at(batch, gm, is64);
            float4 s0 = make_float4(0.f, 0.f, 0.f, 0.f);
            float4 s1 = make_float4(0.f, 0.f, 0.f, 0.f);
            while (i < TM) {
                int gm2 = row0 + ty * TM + i;
                if (gm2 >= M || idx_at(batch, gm2, is64) != g) break;
                s0.x += fmaxf(acc[i][0] + bv[0], 0.f);
                s0.y += fmaxf(acc[i][1] + bv[1], 0.f);
                s0.z += fmaxf(acc[i][2] + bv[2], 0.f);
                s0.w += fmaxf(acc[i][3] + bv[3], 0.f);
                s1.x += fmaxf(acc[i][4] + bv[4], 0.f);
                s1.y += fmaxf(acc[i][5] + bv[5], 0.f);
                s1.z += fmaxf(acc[i][6] + bv[6], 0.f);
                s1.w += fmaxf(acc[i][7] + bv[7], 0.f);
                i++;
            }
            float* dst = g_sums + g * HID + col0 + tx * TN;
            red_add_v4(dst, s0);
            red_add_v4(dst + 4, s1);
        }
    }
}

// ---------------------------------------------------------------------------
// Final: pooled @ fc_w + fc_b, log_softmax
// ---------------------------------------------------------------------------
__global__ void k_final(const float* __restrict__ fcw, const float* __restrict__ fcb,
                        float* __restrict__ out) {
    int g = threadIdx.x;
    if (g >= N_GRAPHS) return;
    float inv = 1.0f / fmaxf(g_cnt[g], 1.0f);
    float l0 = fcb[0], l1 = fcb[1];
#pragma unroll 8
    for (int f = 0; f < HID; f++) {
        float p = g_sums[g * HID + f] * inv;
        l0 += p * fcw[f * N_CLS + 0];
        l1 += p * fcw[f * N_CLS + 1];
    }
    float m = fmaxf(l0, l1);
    float lse = m + logf(expf(l0 - m) + expf(l1 - m));
    out[g * N_CLS + 0] = l0 - lse;
    out[g * N_CLS + 1] = l1 - lse;
}

// ---------------------------------------------------------------------------
extern "C" void kernel_launch(void* const* d_in, const int* in_sizes, int n_in,
                              void* d_out, int out_size) {
    const float* x     = (const float*)d_in[0];
    const void*  edges = d_in[1];
    const void*  batch = d_in[2];
    const float* W1    = (const float*)d_in[3];
    const float* b1    = (const float*)d_in[4];
    const float* W2    = (const float*)d_in[5];
    const float* b2    = (const float*)d_in[6];
    const float* fcw   = (const float*)d_in[7];
    const float* fcb   = (const float*)d_in[8];
    float* out = (float*)d_out;

    const int T = 256;

    k_prep<<<(N_NODES + T - 1) / T, T>>>(edges);
    k_deg_cnt<<<(N_EDGES + T - 1) / T, T>>>(edges, batch);
    k_scan_rsqrt<<<1, 1024>>>();
    k_fill<<<(N_EDGES + T - 1) / T, T>>>(edges);

    // Layer 1: agg (F=128) then GEMM(128->256)+relu
    {
        long long nthr = (long long)N_NODES * 32;
        k_agg<F_IN><<<(unsigned)((nthr + 255) / 256), 256>>>(x, g_buf2);
        dim3 grid(HID / 64, (N_NODES + 127) / 128);
        k_gemm<false><<<grid, 128>>>(g_buf2, W1, b1, g_buf1, batch,
                                     N_NODES, HID, F_IN);
    }
    // Layer 2: agg (F=256) then GEMM(256->256)+relu fused with pooling
    {
        long long nthr = (long long)N_NODES * 32;
        k_agg<HID><<<(unsigned)((nthr + 255) / 256), 256>>>(g_buf1, g_buf2);
        dim3 grid(HID / 64, (N_NODES + 127) / 128);
        k_gemm<true><<<grid, 128>>>(g_buf2, W2, b2, nullptr, batch,
                                    N_NODES, HID, HID);
    }
    k_final<<<1, 64>>>(fcw, fcb, out);
}